// round 1
// baseline (speedup 1.0000x reference)
#include <cuda_runtime.h>
#include <math.h>

#define N_NODES 10000
#define N_EDGES 160000
#define N_GRAPHS 64
#define HID 128
#define LAT 64
#define NLAY 3
#define ET 32          // edges per block in the edge kernel

// ---------------- device scratch (no allocations allowed) ----------------
__device__ float d_h[N_NODES * HID];
__device__ float d_aggr[N_NODES * HID];
__device__ float d_W1t[NLAY * 257 * 256];   // msg1_W transposed: [l][k(257)][j(256)]
__device__ float d_W2t[NLAY * 256 * HID];   // msg2_W transposed: [l][k(256)][i(128)]
__device__ float d_Wgt[NLAY * 256 * HID];   // gate_W transposed: [l][k(256)][j(128)]
__device__ float d_sums[N_GRAPHS * HID];
__device__ float d_counts[N_GRAPHS];

__device__ __forceinline__ float sigmoidf_(float v) {
    return 1.f / (1.f + __expf(-v));
}

// block-wide sum over blockDim.x==128 threads
__device__ __forceinline__ float block_sum128(float v, float* red, int j) {
    red[j] = v;
    __syncthreads();
    #pragma unroll
    for (int s = 64; s > 0; s >>= 1) {
        if (j < s) red[j] += red[j + s];
        __syncthreads();
    }
    float r = red[0];
    __syncthreads();
    return r;
}

// ---------------- weight transposes (run once per launch) ----------------
__global__ void transpose_kernel(const float* __restrict__ W1,   // [3][256][257]
                                 const float* __restrict__ W2,   // [3][128][256]
                                 const float* __restrict__ Wg) { // [3][128][256]
    int idx = blockIdx.x * blockDim.x + threadIdx.x;
    int stride = gridDim.x * blockDim.x;
    const int n1 = NLAY * 256 * 257;
    for (int t = idx; t < n1; t += stride) {
        int l = t / (256 * 257);
        int r = t % (256 * 257);
        int j = r / 257;
        int k = r % 257;
        d_W1t[l * 257 * 256 + k * 256 + j] = W1[t];
    }
    const int n2 = NLAY * 128 * 256;
    for (int t = idx; t < n2; t += stride) {
        int l = t / (128 * 256);
        int r = t % (128 * 256);
        int i = r / 256;
        int k = r % 256;
        d_W2t[l * 256 * 128 + k * 128 + i] = W2[t];
        d_Wgt[l * 256 * 128 + k * 128 + i] = Wg[t];
    }
}

// ---------------- node embedding: h = silu(LN(x @ W.T + b)) ----------------
__global__ void embed_kernel(const float* __restrict__ x,
                             const float* __restrict__ W,   // [128][3]
                             const float* __restrict__ b,
                             const float* __restrict__ lng,
                             const float* __restrict__ lnb) {
    __shared__ float red[HID];
    int n = blockIdx.x;
    int j = threadIdx.x;
    float x0 = x[n * 3 + 0], x1 = x[n * 3 + 1], x2 = x[n * 3 + 2];
    float v = b[j] + x0 * W[j * 3 + 0] + x1 * W[j * 3 + 1] + x2 * W[j * 3 + 2];
    float m = block_sum128(v, red, j) * (1.f / HID);
    float d = v - m;
    float var = block_sum128(d * d, red, j) * (1.f / HID);
    float y = d * rsqrtf(var + 1e-5f) * lng[j] + lnb[j];
    d_h[n * HID + j] = y * sigmoidf_(y);
}

// ---------------- zero scratch ----------------
__global__ void zero_aggr_kernel() {
    int idx = blockIdx.x * blockDim.x + threadIdx.x;
    int stride = gridDim.x * blockDim.x;
    for (int t = idx; t < N_NODES * HID; t += stride) d_aggr[t] = 0.f;
}
__global__ void zero_pool_kernel() {
    int idx = blockIdx.x * blockDim.x + threadIdx.x;
    if (idx < N_GRAPHS * HID) d_sums[idx] = 0.f;
    if (idx < N_GRAPHS) d_counts[idx] = 0.f;
}

// ---------------- edge MLP + scatter-add (the hot kernel) ----------------
// block = 256 threads, ET=32 edges/block.
// GEMM1: m1[e][j] = silu(b1[j] + sum_k z[e][k] * W1t[k][j]),  k in [0,257)
// GEMM2: m2[e][i] = b2[i] + sum_j m1[e][j] * W2t[j][i]
// atomicAdd into aggr[dst[e]][i]
__global__ void __launch_bounds__(256) edge_kernel(
    const float* __restrict__ edge_attr,
    const int* __restrict__ edge_index,
    const float* __restrict__ b1_all,   // [3][256]
    const float* __restrict__ b2_all,   // [3][128]
    int l) {
    // zbuf doubles as: z [32][260] (33280 B) then m1 [32][256] (32768 B)
    __shared__ __align__(16) float zbuf[ET * 260];
    __shared__ int dst_s[ET];
    __shared__ int src_s[ET];

    const int tid = threadIdx.x;
    const int e0 = blockIdx.x * ET;
    const float* W1 = d_W1t + l * 257 * 256;
    const float* W2 = d_W2t + l * 256 * HID;

    if (tid < ET)                dst_s[tid]       = edge_index[N_EDGES + e0 + tid];
    else if (tid < 2 * ET)       src_s[tid - ET]  = edge_index[e0 + tid - ET];
    __syncthreads();

    // stage z = [h[dst] | h[src] | ea]
    for (int e = 0; e < ET; ++e) {
        float v;
        if (tid < HID) v = d_h[dst_s[e] * HID + tid];
        else           v = d_h[src_s[e] * HID + (tid - HID)];
        zbuf[e * 260 + tid] = v;
        if (tid == 0) zbuf[e * 260 + 256] = edge_attr[e0 + e];
    }
    __syncthreads();

    // ---- GEMM1: thread j owns output column j for all 32 edges ----
    const int j = tid;
    float acc[ET];
    {
        float bj = b1_all[l * 256 + j];
        #pragma unroll
        for (int e = 0; e < ET; ++e) acc[e] = bj;
    }
    for (int k = 0; k < 256; k += 4) {
        float w0 = W1[(k + 0) * 256 + j];
        float w1 = W1[(k + 1) * 256 + j];
        float w2 = W1[(k + 2) * 256 + j];
        float w3 = W1[(k + 3) * 256 + j];
        #pragma unroll
        for (int e = 0; e < ET; ++e) {
            float4 zv = *(const float4*)&zbuf[e * 260 + k];
            acc[e] = fmaf(zv.x, w0, acc[e]);
            acc[e] = fmaf(zv.y, w1, acc[e]);
            acc[e] = fmaf(zv.z, w2, acc[e]);
            acc[e] = fmaf(zv.w, w3, acc[e]);
        }
    }
    {   // edge_attr column (k = 256)
        float wl = W1[256 * 256 + j];
        #pragma unroll
        for (int e = 0; e < ET; ++e) acc[e] = fmaf(zbuf[e * 260 + 256], wl, acc[e]);
    }
    __syncthreads();   // all z reads complete before overwriting buffer

    // silu, store m1 as [e][256]
    #pragma unroll
    for (int e = 0; e < ET; ++e) {
        float v = acc[e];
        zbuf[e * 256 + j] = v * sigmoidf_(v);
    }
    __syncthreads();

    // ---- GEMM2: thread (i, e-half) owns 16 edges for column i ----
    const int i = tid & (HID - 1);
    const int ebase = (tid >> 7) * 16;
    float acc2[16];
    #pragma unroll
    for (int e = 0; e < 16; ++e) acc2[e] = 0.f;
    #pragma unroll 2
    for (int jj = 0; jj < 256; ++jj) {
        float w = W2[jj * HID + i];
        #pragma unroll
        for (int e = 0; e < 16; ++e)
            acc2[e] = fmaf(zbuf[(ebase + e) * 256 + jj], w, acc2[e]);
    }
    float bi = b2_all[l * HID + i];
    #pragma unroll
    for (int e = 0; e < 16; ++e)
        atomicAdd(&d_aggr[dst_s[ebase + e] * HID + i], acc2[e] + bi);
}

// ---------------- gated node update + residual + LN ----------------
__global__ void node_kernel(const float* __restrict__ gb_all,  // [3][128]
                            const float* __restrict__ lng_all, // [3][128]
                            const float* __restrict__ lnb_all, // [3][128]
                            int l) {
    __shared__ float hn[HID], an[HID], red[HID];
    int n = blockIdx.x;
    int j = threadIdx.x;
    hn[j] = d_h[n * HID + j];
    an[j] = d_aggr[n * HID + j];
    __syncthreads();

    const float* Wg = d_Wgt + l * 256 * HID;
    float g = gb_all[l * HID + j];
    #pragma unroll 4
    for (int k = 0; k < HID; ++k) g = fmaf(hn[k], Wg[k * HID + j], g);
    #pragma unroll 4
    for (int k = 0; k < HID; ++k) g = fmaf(an[k], Wg[(HID + k) * HID + j], g);
    g = sigmoidf_(g);

    float hnew = g * an[j] + (1.f - g) * hn[j];
    float t = hn[j] + hnew;
    float m = block_sum128(t, red, j) * (1.f / HID);
    float d = t - m;
    float var = block_sum128(d * d, red, j) * (1.f / HID);
    d_h[n * HID + j] = d * rsqrtf(var + 1e-5f) * lng_all[l * HID + j] + lnb_all[l * HID + j];
}

// ---------------- pooling: per-graph sums and counts ----------------
__global__ void pool_kernel(const int* __restrict__ batch) {
    int n = blockIdx.x;
    int j = threadIdx.x;
    int g = batch[n];
    atomicAdd(&d_sums[g * HID + j], d_h[n * HID + j]);
    if (j == 0) atomicAdd(&d_counts[g], 1.f);
}

// ---------------- x_global + projector; writes d_out ----------------
// out layout: z_out [64][64] at [0,4096), x_global [64][128] at [4096,12288)
__global__ void final_kernel(const float* __restrict__ W1, const float* __restrict__ b1,
                             const float* __restrict__ g1, const float* __restrict__ bb1,
                             const float* __restrict__ W2, const float* __restrict__ b2,
                             const float* __restrict__ g2, const float* __restrict__ bb2,
                             float* __restrict__ out) {
    __shared__ float xg[HID], p[HID], red[HID];
    int gr = blockIdx.x;
    int j = threadIdx.x;

    float c = d_counts[gr];
    float scale = 1.f / fmaxf(c, 1.f) + 1.f / (c + 1e-6f);
    float v = d_sums[gr * HID + j] * scale;
    xg[j] = v;
    out[N_GRAPHS * LAT + gr * HID + j] = v;   // x_global
    __syncthreads();

    // proj1 + LN + silu
    float a = b1[j];
    #pragma unroll 4
    for (int k = 0; k < HID; ++k) a = fmaf(xg[k], W1[j * HID + k], a);
    float m = block_sum128(a, red, j) * (1.f / HID);
    float d = a - m;
    float var = block_sum128(d * d, red, j) * (1.f / HID);
    a = d * rsqrtf(var + 1e-5f) * g1[j] + bb1[j];
    a = a * sigmoidf_(a);
    p[j] = a;
    __syncthreads();

    // proj2 (64 outputs) + LN over 64
    float z = 0.f;
    if (j < LAT) {
        z = b2[j];
        #pragma unroll 4
        for (int k = 0; k < HID; ++k) z = fmaf(p[k], W2[j * HID + k], z);
    }
    float m2 = block_sum128((j < LAT) ? z : 0.f, red, j) * (1.f / LAT);
    float d2 = z - m2;
    float var2 = block_sum128((j < LAT) ? d2 * d2 : 0.f, red, j) * (1.f / LAT);
    if (j < LAT)
        out[gr * LAT + j] = d2 * rsqrtf(var2 + 1e-5f) * g2[j] + bb2[j];
}

// ---------------- launch ----------------
extern "C" void kernel_launch(void* const* d_in, const int* in_sizes, int n_in,
                              void* d_out, int out_size) {
    const float* x        = (const float*)d_in[0];
    const float* ea       = (const float*)d_in[1];
    const int*   ei       = (const int*)  d_in[2];
    const int*   batch    = (const int*)  d_in[3];
    const float* embW     = (const float*)d_in[4];
    const float* embb     = (const float*)d_in[5];
    const float* embg     = (const float*)d_in[6];
    const float* emblb    = (const float*)d_in[7];
    const float* m1W      = (const float*)d_in[8];
    const float* m1b      = (const float*)d_in[9];
    const float* m2W      = (const float*)d_in[10];
    const float* m2b      = (const float*)d_in[11];
    const float* gW       = (const float*)d_in[12];
    const float* gb       = (const float*)d_in[13];
    const float* lng      = (const float*)d_in[14];
    const float* lnb      = (const float*)d_in[15];
    const float* p1W      = (const float*)d_in[16];
    const float* p1b      = (const float*)d_in[17];
    const float* pl1g     = (const float*)d_in[18];
    const float* pl1b     = (const float*)d_in[19];
    const float* p2W      = (const float*)d_in[20];
    const float* p2b      = (const float*)d_in[21];
    const float* pl2g     = (const float*)d_in[22];
    const float* pl2b     = (const float*)d_in[23];
    float* out = (float*)d_out;

    transpose_kernel<<<384, 256>>>(m1W, m2W, gW);
    embed_kernel<<<N_NODES, HID>>>(x, embW, embb, embg, emblb);

    for (int l = 0; l < NLAY; ++l) {
        zero_aggr_kernel<<<640, 256>>>();
        edge_kernel<<<N_EDGES / ET, 256>>>(ea, ei, m1b, m2b, l);
        node_kernel<<<N_NODES, HID>>>(gb, lng, lnb, l);
    }

    zero_pool_kernel<<<33, 256>>>();
    pool_kernel<<<N_NODES, HID>>>(batch);
    final_kernel<<<N_GRAPHS, HID>>>(p1W, p1b, pl1g, pl1b, p2W, p2b, pl2g, pl2b, out);
}

// round 3
// speedup vs baseline: 2.1031x; 2.1031x over previous
#include <cuda_runtime.h>
#include <math.h>

#define N_NODES 10000
#define N_EDGES 160000
#define N_GRAPHS 64
#define HID 128
#define LAT 64
#define NLAY 3
#define ET 32          // edges per block in the edge kernel

// ---------------- device scratch (no allocations allowed) ----------------
__device__ float d_h[N_NODES * HID];
__device__ float d_aggr[N_NODES * HID];
__device__ float d_W1t[NLAY * 257 * 256];   // msg1_W transposed: [l][k(257)][j(256)]
__device__ float d_W2t[NLAY * 256 * HID];   // msg2_W transposed: [l][k(256)][i(128)]
__device__ float d_Wgt[NLAY * 256 * HID];   // gate_W transposed: [l][k(256)][j(128)]
__device__ float d_sums[N_GRAPHS * HID];
__device__ float d_counts[N_GRAPHS];

__device__ __forceinline__ float sigmoidf_(float v) {
    return 1.f / (1.f + __expf(-v));
}

// block-wide sum over blockDim.x==128 threads
__device__ __forceinline__ float block_sum128(float v, float* red, int j) {
    red[j] = v;
    __syncthreads();
    #pragma unroll
    for (int s = 64; s > 0; s >>= 1) {
        if (j < s) red[j] += red[j + s];
        __syncthreads();
    }
    float r = red[0];
    __syncthreads();
    return r;
}

// ---------------- weight transposes (run once per launch) ----------------
__global__ void transpose_kernel(const float* __restrict__ W1,   // [3][256][257]
                                 const float* __restrict__ W2,   // [3][128][256]
                                 const float* __restrict__ Wg) { // [3][128][256]
    int idx = blockIdx.x * blockDim.x + threadIdx.x;
    int stride = gridDim.x * blockDim.x;
    const int n1 = NLAY * 256 * 257;
    for (int t = idx; t < n1; t += stride) {
        int l = t / (256 * 257);
        int r = t % (256 * 257);
        int j = r / 257;
        int k = r % 257;
        d_W1t[l * 257 * 256 + k * 256 + j] = W1[t];
    }
    const int n2 = NLAY * 128 * 256;
    for (int t = idx; t < n2; t += stride) {
        int l = t / (128 * 256);
        int r = t % (128 * 256);
        int i = r / 256;
        int k = r % 256;
        d_W2t[l * 256 * 128 + k * 128 + i] = W2[t];
        d_Wgt[l * 256 * 128 + k * 128 + i] = Wg[t];
    }
}

// ---------------- node embedding: h = silu(LN(x @ W.T + b)) ----------------
__global__ void embed_kernel(const float* __restrict__ x,
                             const float* __restrict__ W,   // [128][3]
                             const float* __restrict__ b,
                             const float* __restrict__ lng,
                             const float* __restrict__ lnb) {
    __shared__ float red[HID];
    int n = blockIdx.x;
    int j = threadIdx.x;
    float x0 = x[n * 3 + 0], x1 = x[n * 3 + 1], x2 = x[n * 3 + 2];
    float v = b[j] + x0 * W[j * 3 + 0] + x1 * W[j * 3 + 1] + x2 * W[j * 3 + 2];
    float m = block_sum128(v, red, j) * (1.f / HID);
    float d = v - m;
    float var = block_sum128(d * d, red, j) * (1.f / HID);
    float y = d * rsqrtf(var + 1e-5f) * lng[j] + lnb[j];
    d_h[n * HID + j] = y * sigmoidf_(y);
}

// ---------------- zero scratch ----------------
__global__ void zero_aggr_kernel() {
    int idx = blockIdx.x * blockDim.x + threadIdx.x;
    int stride = gridDim.x * blockDim.x;
    for (int t = idx; t < N_NODES * HID; t += stride) d_aggr[t] = 0.f;
}
__global__ void zero_pool_kernel() {
    int idx = blockIdx.x * blockDim.x + threadIdx.x;
    if (idx < N_GRAPHS * HID) d_sums[idx] = 0.f;
    if (idx < N_GRAPHS) d_counts[idx] = 0.f;
}

// ---------------- edge MLP + scatter-add (the hot kernel) ----------------
// block = 256 threads, ET=32 edges/block.
// GEMM1: 128 j-threads x 2 edge-groups; each thread owns cols {j, j+128} for 16 edges.
//        per k-group of 4: 16 LDS.128 : 128 FMA  (8 FMA per LDS)
// GEMM2: 64 i-threads x 4 edge-groups; each thread owns cols {i, i+64} for 8 edges.
//        per jj-group of 4: 8 LDS.128 : 64 FMA   (8 FMA per LDS)
__global__ void __launch_bounds__(256) edge_kernel(
    const float* __restrict__ edge_attr,
    const int* __restrict__ edge_index,
    const float* __restrict__ b1_all,   // [3][256]
    const float* __restrict__ b2_all,   // [3][128]
    int l) {
    // zbuf doubles as: z [32][260] (33280 B) then m1 [32][256] (32768 B)
    __shared__ __align__(16) float zbuf[ET * 260];
    __shared__ int dst_s[ET];
    __shared__ int src_s[ET];

    const int tid = threadIdx.x;
    const int e0 = blockIdx.x * ET;
    const float* W1 = d_W1t + l * 257 * 256;
    const float* W2 = d_W2t + l * 256 * HID;

    if (tid < ET)                dst_s[tid]       = edge_index[N_EDGES + e0 + tid];
    else if (tid < 2 * ET)       src_s[tid - ET]  = edge_index[e0 + tid - ET];
    __syncthreads();

    // stage z = [h[dst] | h[src] | ea]
    for (int e = 0; e < ET; ++e) {
        float v;
        if (tid < HID) v = d_h[dst_s[e] * HID + tid];
        else           v = d_h[src_s[e] * HID + (tid - HID)];
        zbuf[e * 260 + tid] = v;
        if (tid == 0) zbuf[e * 260 + 256] = edge_attr[e0 + e];
    }
    __syncthreads();

    // ---- GEMM1 ----
    const int j1 = tid & 127;          // column (also col j1+128)
    const int eg1 = (tid >> 7) * 16;   // 16-edge group base
    float acc[2][16];
    {
        float b0 = b1_all[l * 256 + j1];
        float b1v = b1_all[l * 256 + j1 + 128];
        #pragma unroll
        for (int e = 0; e < 16; ++e) { acc[0][e] = b0; acc[1][e] = b1v; }
    }
    for (int k = 0; k < 256; k += 4) {
        float wa0 = W1[(k + 0) * 256 + j1];
        float wa1 = W1[(k + 1) * 256 + j1];
        float wa2 = W1[(k + 2) * 256 + j1];
        float wa3 = W1[(k + 3) * 256 + j1];
        float wb0 = W1[(k + 0) * 256 + j1 + 128];
        float wb1 = W1[(k + 1) * 256 + j1 + 128];
        float wb2 = W1[(k + 2) * 256 + j1 + 128];
        float wb3 = W1[(k + 3) * 256 + j1 + 128];
        #pragma unroll
        for (int e = 0; e < 16; ++e) {
            float4 zv = *(const float4*)&zbuf[(eg1 + e) * 260 + k];
            acc[0][e] = fmaf(zv.x, wa0, acc[0][e]);
            acc[0][e] = fmaf(zv.y, wa1, acc[0][e]);
            acc[0][e] = fmaf(zv.z, wa2, acc[0][e]);
            acc[0][e] = fmaf(zv.w, wa3, acc[0][e]);
            acc[1][e] = fmaf(zv.x, wb0, acc[1][e]);
            acc[1][e] = fmaf(zv.y, wb1, acc[1][e]);
            acc[1][e] = fmaf(zv.z, wb2, acc[1][e]);
            acc[1][e] = fmaf(zv.w, wb3, acc[1][e]);
        }
    }
    {   // edge_attr column (k = 256)
        float wa = W1[256 * 256 + j1];
        float wb = W1[256 * 256 + j1 + 128];
        #pragma unroll
        for (int e = 0; e < 16; ++e) {
            float zl = zbuf[(eg1 + e) * 260 + 256];
            acc[0][e] = fmaf(zl, wa, acc[0][e]);
            acc[1][e] = fmaf(zl, wb, acc[1][e]);
        }
    }
    __syncthreads();   // all z reads complete before overwriting buffer

    // silu, store m1 as [e][256]
    #pragma unroll
    for (int e = 0; e < 16; ++e) {
        float v0 = acc[0][e];
        float v1 = acc[1][e];
        zbuf[(eg1 + e) * 256 + j1]       = v0 * sigmoidf_(v0);
        zbuf[(eg1 + e) * 256 + j1 + 128] = v1 * sigmoidf_(v1);
    }
    __syncthreads();

    // ---- GEMM2 ----
    const int i2 = tid & 63;          // column (also col i2+64)
    const int eg2 = (tid >> 6) * 8;   // 8-edge group base
    float acc2[2][8];
    #pragma unroll
    for (int e = 0; e < 8; ++e) { acc2[0][e] = 0.f; acc2[1][e] = 0.f; }
    for (int jj = 0; jj < 256; jj += 4) {
        float wa0 = W2[(jj + 0) * HID + i2];
        float wa1 = W2[(jj + 1) * HID + i2];
        float wa2 = W2[(jj + 2) * HID + i2];
        float wa3 = W2[(jj + 3) * HID + i2];
        float wb0 = W2[(jj + 0) * HID + i2 + 64];
        float wb1 = W2[(jj + 1) * HID + i2 + 64];
        float wb2 = W2[(jj + 2) * HID + i2 + 64];
        float wb3 = W2[(jj + 3) * HID + i2 + 64];
        #pragma unroll
        for (int e = 0; e < 8; ++e) {
            float4 mv = *(const float4*)&zbuf[(eg2 + e) * 256 + jj];
            acc2[0][e] = fmaf(mv.x, wa0, acc2[0][e]);
            acc2[0][e] = fmaf(mv.y, wa1, acc2[0][e]);
            acc2[0][e] = fmaf(mv.z, wa2, acc2[0][e]);
            acc2[0][e] = fmaf(mv.w, wa3, acc2[0][e]);
            acc2[1][e] = fmaf(mv.x, wb0, acc2[1][e]);
            acc2[1][e] = fmaf(mv.y, wb1, acc2[1][e]);
            acc2[1][e] = fmaf(mv.z, wb2, acc2[1][e]);
            acc2[1][e] = fmaf(mv.w, wb3, acc2[1][e]);
        }
    }
    float bi0 = b2_all[l * HID + i2];
    float bi1 = b2_all[l * HID + i2 + 64];
    #pragma unroll
    for (int e = 0; e < 8; ++e) {
        int d = dst_s[eg2 + e];
        atomicAdd(&d_aggr[d * HID + i2],      acc2[0][e] + bi0);
        atomicAdd(&d_aggr[d * HID + i2 + 64], acc2[1][e] + bi1);
    }
}

// ---------------- gated node update + residual + LN ----------------
__global__ void node_kernel(const float* __restrict__ gb_all,  // [3][128]
                            const float* __restrict__ lng_all, // [3][128]
                            const float* __restrict__ lnb_all, // [3][128]
                            int l) {
    __shared__ float hn[HID], an[HID], red[HID];
    int n = blockIdx.x;
    int j = threadIdx.x;
    hn[j] = d_h[n * HID + j];
    an[j] = d_aggr[n * HID + j];
    __syncthreads();

    const float* Wg = d_Wgt + l * 256 * HID;
    float g = gb_all[l * HID + j];
    #pragma unroll 4
    for (int k = 0; k < HID; ++k) g = fmaf(hn[k], Wg[k * HID + j], g);
    #pragma unroll 4
    for (int k = 0; k < HID; ++k) g = fmaf(an[k], Wg[(HID + k) * HID + j], g);
    g = sigmoidf_(g);

    float hnew = g * an[j] + (1.f - g) * hn[j];
    float t = hn[j] + hnew;
    float m = block_sum128(t, red, j) * (1.f / HID);
    float d = t - m;
    float var = block_sum128(d * d, red, j) * (1.f / HID);
    d_h[n * HID + j] = d * rsqrtf(var + 1e-5f) * lng_all[l * HID + j] + lnb_all[l * HID + j];
}

// ---------------- pooling: per-graph sums and counts ----------------
__global__ void pool_kernel(const int* __restrict__ batch) {
    int n = blockIdx.x;
    int j = threadIdx.x;
    int g = batch[n];
    atomicAdd(&d_sums[g * HID + j], d_h[n * HID + j]);
    if (j == 0) atomicAdd(&d_counts[g], 1.f);
}

// ---------------- x_global + projector; writes d_out ----------------
// out layout: z_out [64][64] at [0,4096), x_global [64][128] at [4096,12288)
__global__ void final_kernel(const float* __restrict__ W1, const float* __restrict__ b1,
                             const float* __restrict__ g1, const float* __restrict__ bb1,
                             const float* __restrict__ W2, const float* __restrict__ b2,
                             const float* __restrict__ g2, const float* __restrict__ bb2,
                             float* __restrict__ out) {
    __shared__ float xg[HID], p[HID], red[HID];
    int gr = blockIdx.x;
    int j = threadIdx.x;

    float c = d_counts[gr];
    float scale = 1.f / fmaxf(c, 1.f) + 1.f / (c + 1e-6f);
    float v = d_sums[gr * HID + j] * scale;
    xg[j] = v;
    out[N_GRAPHS * LAT + gr * HID + j] = v;   // x_global
    __syncthreads();

    // proj1 + LN + silu
    float a = b1[j];
    #pragma unroll 4
    for (int k = 0; k < HID; ++k) a = fmaf(xg[k], W1[j * HID + k], a);
    float m = block_sum128(a, red, j) * (1.f / HID);
    float d = a - m;
    float var = block_sum128(d * d, red, j) * (1.f / HID);
    a = d * rsqrtf(var + 1e-5f) * g1[j] + bb1[j];
    a = a * sigmoidf_(a);
    p[j] = a;
    __syncthreads();

    // proj2 (64 outputs) + LN over 64
    float z = 0.f;
    if (j < LAT) {
        z = b2[j];
        #pragma unroll 4
        for (int k = 0; k < HID; ++k) z = fmaf(p[k], W2[j * HID + k], z);
    }
    float m2 = block_sum128((j < LAT) ? z : 0.f, red, j) * (1.f / LAT);
    float d2 = z - m2;
    float var2 = block_sum128((j < LAT) ? d2 * d2 : 0.f, red, j) * (1.f / LAT);
    if (j < LAT)
        out[gr * LAT + j] = d2 * rsqrtf(var2 + 1e-5f) * g2[j] + bb2[j];
}

// ---------------- launch ----------------
extern "C" void kernel_launch(void* const* d_in, const int* in_sizes, int n_in,
                              void* d_out, int out_size) {
    const float* x        = (const float*)d_in[0];
    const float* ea       = (const float*)d_in[1];
    const int*   ei       = (const int*)  d_in[2];
    const int*   batch    = (const int*)  d_in[3];
    const float* embW     = (const float*)d_in[4];
    const float* embb     = (const float*)d_in[5];
    const float* embg     = (const float*)d_in[6];
    const float* emblb    = (const float*)d_in[7];
    const float* m1W      = (const float*)d_in[8];
    const float* m1b      = (const float*)d_in[9];
    const float* m2W      = (const float*)d_in[10];
    const float* m2b      = (const float*)d_in[11];
    const float* gW       = (const float*)d_in[12];
    const float* gb       = (const float*)d_in[13];
    const float* lng      = (const float*)d_in[14];
    const float* lnb      = (const float*)d_in[15];
    const float* p1W      = (const float*)d_in[16];
    const float* p1b      = (const float*)d_in[17];
    const float* pl1g     = (const float*)d_in[18];
    const float* pl1b     = (const float*)d_in[19];
    const float* p2W      = (const float*)d_in[20];
    const float* p2b      = (const float*)d_in[21];
    const float* pl2g     = (const float*)d_in[22];
    const float* pl2b     = (const float*)d_in[23];
    float* out = (float*)d_out;

    transpose_kernel<<<384, 256>>>(m1W, m2W, gW);
    embed_kernel<<<N_NODES, HID>>>(x, embW, embb, embg, emblb);

    for (int l = 0; l < NLAY; ++l) {
        zero_aggr_kernel<<<640, 256>>>();
        edge_kernel<<<N_EDGES / ET, 256>>>(ea, ei, m1b, m2b, l);
        node_kernel<<<N_NODES, HID>>>(gb, lng, lnb, l);
    }

    zero_pool_kernel<<<33, 256>>>();
    pool_kernel<<<N_NODES, HID>>>(batch);
    final_kernel<<<N_GRAPHS, HID>>>(p1W, p1b, pl1g, pl1b, p2W, p2b, pl2g, pl2b, out);
}